// round 2
// baseline (speedup 1.0000x reference)
#include <cuda_runtime.h>
#include <cuda_bf16.h>

// Problem constants (ResNHConv_274877907666): B=1, N=196608, NH=9, F=64.
#define F_DIM   64
#define NH_DIM  9
#define MAX_N   196608

#define GCONV_BLOCK 512
#define W_ELEMS (NH_DIM * F_DIM * F_DIM)      // 36864 floats = 147456 B
#define SMEM_FLOATS (W_ELEMS + 3 * F_DIM)     // + bias + ln_w + ln_b
#define SMEM_BYTES (SMEM_FLOATS * sizeof(float))

// Scratch buffers (no allocation allowed in kernel_launch).
__device__ float g_h1[(size_t)MAX_N * F_DIM];
__device__ float g_h2[(size_t)MAX_N * F_DIM];

// ---------------------------------------------------------------------------
// Kernel 1: h1 = silu(layernorm(x)) ; one warp per 64-float row.
// ---------------------------------------------------------------------------
__global__ void ln_silu_kernel(const float* __restrict__ x,
                               const float* __restrict__ lnw,
                               const float* __restrict__ lnb,
                               float* __restrict__ out, int N)
{
    int row  = blockIdx.x * (blockDim.x >> 5) + (threadIdx.x >> 5);
    int lane = threadIdx.x & 31;
    if (row >= N) return;

    const float2 v = reinterpret_cast<const float2*>(x + (size_t)row * F_DIM)[lane];
    float s  = v.x + v.y;
    float s2 = v.x * v.x + v.y * v.y;
    #pragma unroll
    for (int off = 16; off > 0; off >>= 1) {
        s  += __shfl_xor_sync(0xffffffffu, s,  off);
        s2 += __shfl_xor_sync(0xffffffffu, s2, off);
    }
    const float mu  = s * (1.0f / F_DIM);
    const float var = s2 * (1.0f / F_DIM) - mu * mu;
    const float rs  = rsqrtf(var + 1e-5f);

    const float2 wv = reinterpret_cast<const float2*>(lnw)[lane];
    const float2 bv = reinterpret_cast<const float2*>(lnb)[lane];
    float y0 = (v.x - mu) * rs * wv.x + bv.x;
    float y1 = (v.y - mu) * rs * wv.y + bv.y;
    float2 o;
    o.x = y0 / (1.0f + expf(-y0));
    o.y = y1 / (1.0f + expf(-y1));
    reinterpret_cast<float2*>(out + (size_t)row * F_DIM)[lane] = o;
}

// ---------------------------------------------------------------------------
// Kernel 2/3: gathered multi-head contraction.
//   pre[n,o] = sum_k sum_f hin[adjc[n,k], f] * W[k,f,o]  (+ bias)
// FIRST=true : out = silu(layernorm(pre; lnw, lnb))           (layer 1)
// FIRST=false: out = pre + xres                               (layer 2 + residual)
// One node per thread; 64 fp32 accumulators register-resident; W in smem.
// NOTE: adjc arrives as int32 (JAX default config coerces int64 -> int32).
// ---------------------------------------------------------------------------
template <bool FIRST>
__global__ void __launch_bounds__(GCONV_BLOCK)
gconv_kernel(const float* __restrict__ hin,
             const int* __restrict__ adjc,
             const float* __restrict__ W,
             const float* __restrict__ bias,
             const float* __restrict__ lnw,
             const float* __restrict__ lnb,
             const float* __restrict__ xres,
             float* __restrict__ out, int N)
{
    extern __shared__ float smem[];
    float* sW  = smem;                 // [NH][F][F]
    float* sB  = smem + W_ELEMS;       // [F]
    float* sLW = sB + F_DIM;           // [F]
    float* sLB = sLW + F_DIM;          // [F]

    // Stage weights (coalesced float4 copy).
    const float4* Wg = reinterpret_cast<const float4*>(W);
    float4*       Ws = reinterpret_cast<float4*>(sW);
    for (int i = threadIdx.x; i < W_ELEMS / 4; i += blockDim.x)
        Ws[i] = Wg[i];
    if (threadIdx.x < F_DIM) {
        sB[threadIdx.x]  = bias[threadIdx.x];
        if (FIRST) {
            sLW[threadIdx.x] = lnw[threadIdx.x];
            sLB[threadIdx.x] = lnb[threadIdx.x];
        }
    }
    __syncthreads();

    const int node = blockIdx.x * blockDim.x + threadIdx.x;
    if (node >= N) return;

    float acc[F_DIM];
    #pragma unroll
    for (int o = 0; o < F_DIM; ++o) acc[o] = 0.0f;

    int idx[NH_DIM];
    #pragma unroll
    for (int k = 0; k < NH_DIM; ++k)
        idx[k] = adjc[(size_t)node * NH_DIM + k];

    for (int k = 0; k < NH_DIM; ++k) {
        const float4* hrow = reinterpret_cast<const float4*>(hin + (size_t)idx[k] * F_DIM);
        const float*  wk   = sW + k * (F_DIM * F_DIM);
        #pragma unroll 2
        for (int f4 = 0; f4 < F_DIM / 4; ++f4) {
            const float4 hv = hrow[f4];
            const float hvs[4] = {hv.x, hv.y, hv.z, hv.w};
            #pragma unroll
            for (int j = 0; j < 4; ++j) {
                const float h = hvs[j];
                const float4* wr = reinterpret_cast<const float4*>(wk + (f4 * 4 + j) * F_DIM);
                #pragma unroll
                for (int o4 = 0; o4 < F_DIM / 4; ++o4) {
                    const float4 w = wr[o4];   // broadcast across the warp
                    acc[4 * o4 + 0] += h * w.x;
                    acc[4 * o4 + 1] += h * w.y;
                    acc[4 * o4 + 2] += h * w.z;
                    acc[4 * o4 + 3] += h * w.w;
                }
            }
        }
    }

    float4* orow = reinterpret_cast<float4*>(out + (size_t)node * F_DIM);

    if (FIRST) {
        // + bias, then fused layernorm + silu over the register-resident row.
        float s = 0.0f, s2 = 0.0f;
        #pragma unroll
        for (int o = 0; o < F_DIM; ++o) {
            acc[o] += sB[o];
            s  += acc[o];
            s2 += acc[o] * acc[o];
        }
        const float mu  = s * (1.0f / F_DIM);
        const float var = s2 * (1.0f / F_DIM) - mu * mu;
        const float rs  = rsqrtf(var + 1e-5f);
        #pragma unroll
        for (int o4 = 0; o4 < F_DIM / 4; ++o4) {
            float4 v;
            float y;
            y = (acc[4*o4+0] - mu) * rs * sLW[4*o4+0] + sLB[4*o4+0]; v.x = y / (1.0f + expf(-y));
            y = (acc[4*o4+1] - mu) * rs * sLW[4*o4+1] + sLB[4*o4+1]; v.y = y / (1.0f + expf(-y));
            y = (acc[4*o4+2] - mu) * rs * sLW[4*o4+2] + sLB[4*o4+2]; v.z = y / (1.0f + expf(-y));
            y = (acc[4*o4+3] - mu) * rs * sLW[4*o4+3] + sLB[4*o4+3]; v.w = y / (1.0f + expf(-y));
            orow[o4] = v;
        }
    } else {
        // + bias + residual x.
        const float4* xrow = reinterpret_cast<const float4*>(xres + (size_t)node * F_DIM);
        #pragma unroll
        for (int o4 = 0; o4 < F_DIM / 4; ++o4) {
            const float4 xv = xrow[o4];
            float4 v;
            v.x = acc[4*o4+0] + sB[4*o4+0] + xv.x;
            v.y = acc[4*o4+1] + sB[4*o4+1] + xv.y;
            v.z = acc[4*o4+2] + sB[4*o4+2] + xv.z;
            v.w = acc[4*o4+3] + sB[4*o4+3] + xv.w;
            orow[o4] = v;
        }
    }
}

// ---------------------------------------------------------------------------
// Launch
// ---------------------------------------------------------------------------
extern "C" void kernel_launch(void* const* d_in, const int* in_sizes, int n_in,
                              void* d_out, int out_size)
{
    const float* x     = (const float*)d_in[0];
    const int*   adjc  = (const int*)d_in[1];     // int32 (JAX x64 disabled)
    const float* ln1_w = (const float*)d_in[2];
    const float* ln1_b = (const float*)d_in[3];
    const float* W1    = (const float*)d_in[4];
    const float* b1    = (const float*)d_in[5];
    const float* ln2_w = (const float*)d_in[6];
    const float* ln2_b = (const float*)d_in[7];
    const float* W2    = (const float*)d_in[8];
    const float* b2    = (const float*)d_in[9];
    float*       out   = (float*)d_out;

    const int N = in_sizes[0] / F_DIM;   // B=1

    float* h1 = nullptr;
    float* h2 = nullptr;
    cudaGetSymbolAddress((void**)&h1, g_h1);
    cudaGetSymbolAddress((void**)&h2, g_h2);

    cudaFuncSetAttribute(gconv_kernel<true>,
                         cudaFuncAttributeMaxDynamicSharedMemorySize, SMEM_BYTES);
    cudaFuncSetAttribute(gconv_kernel<false>,
                         cudaFuncAttributeMaxDynamicSharedMemorySize, SMEM_BYTES);

    // 1) h1 = silu(LN(x))
    {
        const int rows_per_block = 256 / 32;
        const int grid = (N + rows_per_block - 1) / rows_per_block;
        ln_silu_kernel<<<grid, 256>>>(x, ln1_w, ln1_b, h1, N);
    }
    // 2) h2 = silu(LN(gather(h1) @ W1 + b1))
    {
        const int grid = (N + GCONV_BLOCK - 1) / GCONV_BLOCK;
        gconv_kernel<true><<<grid, GCONV_BLOCK, SMEM_BYTES>>>(
            h1, adjc, W1, b1, ln2_w, ln2_b, nullptr, h2, N);
    }
    // 3) out = gather(h2) @ W2 + b2 + x
    {
        const int grid = (N + GCONV_BLOCK - 1) / GCONV_BLOCK;
        gconv_kernel<false><<<grid, GCONV_BLOCK, SMEM_BYTES>>>(
            h2, adjc, W2, b2, nullptr, nullptr, x, out, N);
    }
}

// round 5
// speedup vs baseline: 2.8364x; 2.8364x over previous
#include <cuda_runtime.h>
#include <cstdint>

// Problem constants (ResNHConv_274877907666): B=1, N=196608, NH=9, F=64.
#define F_DIM    64
#define NH_DIM   9
#define MAX_N    196608
#define TILE_M   128
#define NTHREADS 128

// ---------------- smem layout (bytes) ----------------
// B = W^T as tf32, [n=64][kk=576] padded stride 580 floats -> conflict-free frag loads
#define B_STRIDE_F 580
#define B_ROW_B    (B_STRIDE_F * 4)                  // 2320
#define SM_B       0
#define SM_B_SIZE  (F_DIM * B_ROW_B)                 // 148480
// A gather tile, [128 rows][64+4 pad] stride 68 floats, double-buffered
#define A_STRIDE_B 272
#define A_BUF_B    (TILE_M * A_STRIDE_B)             // 34816
#define SM_A       SM_B_SIZE                         // 148480
#define SM_IDX     (SM_A + 2 * A_BUF_B)              // 218112
#define SM_BIAS    (SM_IDX + TILE_M * NH_DIM * 4)    // 222720
#define SM_LW      (SM_BIAS + 256)
#define SM_LB      (SM_LW + 256)
#define SM_TOTAL   (SM_LB + 256)                     // 223488 < 227KB limit

// Scratch buffers (no allocation allowed in kernel_launch).
__device__ float g_h1[(size_t)MAX_N * F_DIM];
__device__ float g_h2[(size_t)MAX_N * F_DIM];

// ---------------- PTX helpers ----------------
__device__ __forceinline__ uint32_t smem_u32(const void* p) {
    uint32_t a;
    asm("{ .reg .u64 t; cvta.to.shared.u64 t, %1; cvt.u32.u64 %0, t; }" : "=r"(a) : "l"(p));
    return a;
}
__device__ __forceinline__ uint32_t f2tf32(float v) {
    uint32_t t; asm("cvt.rna.tf32.f32 %0, %1;" : "=r"(t) : "f"(v)); return t;
}
__device__ __forceinline__ uint32_t lds_tf32(uint32_t addr) {
    float v; asm volatile("ld.shared.f32 %0, [%1];" : "=f"(v) : "r"(addr));
    return f2tf32(v);
}
__device__ __forceinline__ uint32_t lds_u32(uint32_t addr) {
    uint32_t v; asm volatile("ld.shared.b32 %0, [%1];" : "=r"(v) : "r"(addr));
    return v;
}
__device__ __forceinline__ void cp16(uint32_t dst, const void* src) {
    asm volatile("cp.async.cg.shared.global [%0], [%1], 16;" :: "r"(dst), "l"(src) : "memory");
}
__device__ __forceinline__ void cp_commit() {
    asm volatile("cp.async.commit_group;" ::: "memory");
}
__device__ __forceinline__ void cp_wait1() {
    asm volatile("cp.async.wait_group 1;" ::: "memory");
}
__device__ __forceinline__ void cp_wait0() {
    asm volatile("cp.async.wait_group 0;" ::: "memory");
}
__device__ __forceinline__ void mma_tf32(float* c,
                                         uint32_t a0, uint32_t a1, uint32_t a2, uint32_t a3,
                                         uint32_t b0, uint32_t b1) {
    asm volatile(
        "mma.sync.aligned.m16n8k8.row.col.f32.tf32.tf32.f32 "
        "{%0,%1,%2,%3}, {%4,%5,%6,%7}, {%8,%9}, {%0,%1,%2,%3};"
        : "+f"(c[0]), "+f"(c[1]), "+f"(c[2]), "+f"(c[3])
        : "r"(a0), "r"(a1), "r"(a2), "r"(a3), "r"(b0), "r"(b1));
}

// ---------------------------------------------------------------------------
// Kernel 1: h1 = silu(layernorm(x)) ; one warp per 64-float row.
// ---------------------------------------------------------------------------
__global__ void ln_silu_kernel(const float* __restrict__ x,
                               const float* __restrict__ lnw,
                               const float* __restrict__ lnb,
                               float* __restrict__ out, int N)
{
    int row  = blockIdx.x * (blockDim.x >> 5) + (threadIdx.x >> 5);
    int lane = threadIdx.x & 31;
    if (row >= N) return;

    const float2 v = reinterpret_cast<const float2*>(x + (size_t)row * F_DIM)[lane];
    float s  = v.x + v.y;
    float s2 = v.x * v.x + v.y * v.y;
    #pragma unroll
    for (int off = 16; off > 0; off >>= 1) {
        s  += __shfl_xor_sync(0xffffffffu, s,  off);
        s2 += __shfl_xor_sync(0xffffffffu, s2, off);
    }
    const float mu  = s * (1.0f / F_DIM);
    const float var = s2 * (1.0f / F_DIM) - mu * mu;
    const float rs  = rsqrtf(var + 1e-5f);

    const float2 wv = reinterpret_cast<const float2*>(lnw)[lane];
    const float2 bv = reinterpret_cast<const float2*>(lnb)[lane];
    float y0 = (v.x - mu) * rs * wv.x + bv.x;
    float y1 = (v.y - mu) * rs * wv.y + bv.y;
    float2 o;
    o.x = y0 / (1.0f + expf(-y0));
    o.y = y1 / (1.0f + expf(-y1));
    reinterpret_cast<float2*>(out + (size_t)row * F_DIM)[lane] = o;
}

// ---------------------------------------------------------------------------
// Persistent tf32 mma.sync gather-GEMM.
//   D[128,64] = sum over 9 heads of A_gather[128,64] @ W_head[64,64]
// FIRST=true : out = silu(LN(D + bias))     FIRST=false: out = D + bias + xres
// 4 warps; warp w owns rows [32w, 32w+32); cp.async double-buffered gather.
// ---------------------------------------------------------------------------
template <bool FIRST>
__global__ void __launch_bounds__(NTHREADS, 1)
gemm_kernel(const float* __restrict__ hin,
            const int* __restrict__ adjc,
            const float* __restrict__ W,
            const float* __restrict__ bias,
            const float* __restrict__ lnw,
            const float* __restrict__ lnb,
            const float* __restrict__ xres,
            float* __restrict__ out,
            int Nnodes, int n_tiles)
{
    extern __shared__ char smem[];
    const uint32_t sbase = smem_u32(smem);

    const int tid  = threadIdx.x;
    const int wid  = tid >> 5;
    const int lane = tid & 31;
    const int gid  = lane >> 2;    // 0..7
    const int tig  = lane & 3;     // 0..3

    int*   sIdx  = (int*)(smem + SM_IDX);
    float* sBias = (float*)(smem + SM_BIAS);
    float* sLw   = (float*)(smem + SM_LW);
    float* sLb   = (float*)(smem + SM_LB);

    // ---- stage B = W^T (tf32) at [n][kk], stride 580 floats ----
    for (int i = tid; i < NH_DIM * F_DIM * F_DIM; i += NTHREADS) {
        const int head = i >> 12;
        const int rem  = i & 4095;
        const int f    = rem >> 6;
        const int n    = rem & 63;
        const int kk   = head * 64 + f;
        *(uint32_t*)(smem + SM_B + n * B_ROW_B + kk * 4) = f2tf32(W[i]);
    }
    if (tid < F_DIM) {
        sBias[tid] = bias[tid];
        if (FIRST) { sLw[tid] = lnw[tid]; sLb[tid] = lnb[tid]; }
    }
    __syncthreads();

    const float* hbase = hin;

    for (int tile = blockIdx.x; tile < n_tiles; tile += gridDim.x) {
        const int base_node = tile * TILE_M;
        const int rows_here = min(TILE_M, Nnodes - base_node);

        // ---- stage adjacency ----
        for (int i = tid; i < TILE_M * NH_DIM; i += NTHREADS)
            sIdx[i] = (i < rows_here * NH_DIM) ? adjc[(size_t)base_node * NH_DIM + i] : 0;
        __syncthreads();

        float acc[2][8][4];
        #pragma unroll
        for (int mf = 0; mf < 2; ++mf)
            #pragma unroll
            for (int j = 0; j < 8; ++j)
                #pragma unroll
                for (int c = 0; c < 4; ++c) acc[mf][j][c] = 0.0f;

        // ---- gather head 0 into buf 0 ----
        {
            const uint32_t abase = sbase + SM_A;
            #pragma unroll
            for (int i = 0; i < 16; ++i) {
                const int e  = i * NTHREADS + tid;
                const int r  = e >> 4;
                const int f4 = e & 15;
                const int idx = sIdx[r * NH_DIM + 0];
                cp16(abase + r * A_STRIDE_B + f4 * 16,
                     hbase + (size_t)idx * F_DIM + f4 * 4);
            }
            cp_commit();
        }

        for (int k = 0; k < NH_DIM; ++k) {
            // prefetch next head
            if (k < NH_DIM - 1) {
                const uint32_t abase = sbase + SM_A + ((k + 1) & 1) * A_BUF_B;
                #pragma unroll
                for (int i = 0; i < 16; ++i) {
                    const int e  = i * NTHREADS + tid;
                    const int r  = e >> 4;
                    const int f4 = e & 15;
                    const int idx = sIdx[r * NH_DIM + (k + 1)];
                    cp16(abase + r * A_STRIDE_B + f4 * 16,
                         hbase + (size_t)idx * F_DIM + f4 * 4);
                }
                cp_commit();
                cp_wait1();
            } else {
                cp_wait0();
            }
            __syncthreads();

            // ---- mma on buf k&1 ----
            const uint32_t aOff = sbase + SM_A + (k & 1) * A_BUF_B
                                + (wid * 32 + gid) * A_STRIDE_B;
            const uint32_t bOff = sbase + SM_B + gid * B_ROW_B + (k * 64 + tig) * 4;

            #pragma unroll
            for (int ks = 0; ks < 8; ++ks) {
                const uint32_t ca = aOff + (ks * 8 + tig) * 4;
                const uint32_t a0 = lds_tf32(ca);
                const uint32_t a1 = lds_tf32(ca + 8  * A_STRIDE_B);
                const uint32_t a2 = lds_tf32(ca + 16);
                const uint32_t a3 = lds_tf32(ca + 8  * A_STRIDE_B + 16);
                const uint32_t a4 = lds_tf32(ca + 16 * A_STRIDE_B);
                const uint32_t a5 = lds_tf32(ca + 24 * A_STRIDE_B);
                const uint32_t a6 = lds_tf32(ca + 16 * A_STRIDE_B + 16);
                const uint32_t a7 = lds_tf32(ca + 24 * A_STRIDE_B + 16);
                #pragma unroll
                for (int j = 0; j < 8; ++j) {
                    const uint32_t cb = bOff + j * 8 * B_ROW_B + ks * 32;
                    const uint32_t b0 = lds_u32(cb);
                    const uint32_t b1 = lds_u32(cb + 16);
                    mma_tf32(acc[0][j], a0, a1, a2, a3, b0, b1);
                    mma_tf32(acc[1][j], a4, a5, a6, a7, b0, b1);
                }
            }
            __syncthreads();
        }

        // ---- epilogue: registers -> global ----
        #pragma unroll
        for (int mf = 0; mf < 2; ++mf) {
            #pragma unroll
            for (int p = 0; p < 2; ++p) {
                const int r    = wid * 32 + mf * 16 + p * 8 + gid;
                const int node = base_node + r;

                float v[16];
                #pragma unroll
                for (int j = 0; j < 8; ++j) {
                    const int c = j * 8 + tig * 2;
                    v[2*j]   = acc[mf][j][p*2]   + sBias[c];
                    v[2*j+1] = acc[mf][j][p*2+1] + sBias[c + 1];
                }

                if (FIRST) {
                    float s = 0.0f, s2 = 0.0f;
                    #pragma unroll
                    for (int e = 0; e < 16; ++e) { s += v[e]; s2 += v[e] * v[e]; }
                    s  += __shfl_xor_sync(0xffffffffu, s, 1);
                    s2 += __shfl_xor_sync(0xffffffffu, s2, 1);
                    s  += __shfl_xor_sync(0xffffffffu, s, 2);
                    s2 += __shfl_xor_sync(0xffffffffu, s2, 2);
                    const float mu  = s * (1.0f / F_DIM);
                    const float var = s2 * (1.0f / F_DIM) - mu * mu;
                    const float rs  = rsqrtf(var + 1e-5f);
                    if (node < Nnodes) {
                        #pragma unroll
                        for (int j = 0; j < 8; ++j) {
                            const int c = j * 8 + tig * 2;
                            float y0 = (v[2*j]   - mu) * rs * sLw[c]   + sLb[c];
                            float y1 = (v[2*j+1] - mu) * rs * sLw[c+1] + sLb[c+1];
                            float2 o;
                            o.x = y0 / (1.0f + expf(-y0));
                            o.y = y1 / (1.0f + expf(-y1));
                            *(float2*)(out + (size_t)node * F_DIM + c) = o;
                        }
                    }
                } else {
                    if (node < Nnodes) {
                        #pragma unroll
                        for (int j = 0; j < 8; ++j) {
                            const int c = j * 8 + tig * 2;
                            const float2 xv = *(const float2*)(xres + (size_t)node * F_DIM + c);
                            float2 o;
                            o.x = v[2*j]   + xv.x;
                            o.y = v[2*j+1] + xv.y;
                            *(float2*)(out + (size_t)node * F_DIM + c) = o;
                        }
                    }
                }
            }
        }
        __syncthreads();
    }
}

// ---------------------------------------------------------------------------
// Launch
// ---------------------------------------------------------------------------
extern "C" void kernel_launch(void* const* d_in, const int* in_sizes, int n_in,
                              void* d_out, int out_size)
{
    const float* x     = (const float*)d_in[0];
    const int*   adjc  = (const int*)d_in[1];     // int32 (JAX x64 disabled)
    const float* ln1_w = (const float*)d_in[2];
    const float* ln1_b = (const float*)d_in[3];
    const float* W1    = (const float*)d_in[4];
    const float* b1    = (const float*)d_in[5];
    const float* ln2_w = (const float*)d_in[6];
    const float* ln2_b = (const float*)d_in[7];
    const float* W2    = (const float*)d_in[8];
    const float* b2    = (const float*)d_in[9];
    float*       out   = (float*)d_out;

    const int N = in_sizes[0] / F_DIM;   // B=1
    const int n_tiles = (N + TILE_M - 1) / TILE_M;

    float* h1 = nullptr;
    float* h2 = nullptr;
    cudaGetSymbolAddress((void**)&h1, g_h1);
    cudaGetSymbolAddress((void**)&h2, g_h2);

    cudaFuncSetAttribute(gemm_kernel<true>,
                         cudaFuncAttributeMaxDynamicSharedMemorySize, SM_TOTAL);
    cudaFuncSetAttribute(gemm_kernel<false>,
                         cudaFuncAttributeMaxDynamicSharedMemorySize, SM_TOTAL);

    // 1) h1 = silu(LN(x))
    {
        const int rows_per_block = 256 / 32;
        const int grid = (N + rows_per_block - 1) / rows_per_block;
        ln_silu_kernel<<<grid, 256>>>(x, ln1_w, ln1_b, h1, N);
    }
    const int grid = 148;
    // 2) h2 = silu(LN(gather(h1) @ W1 + b1))
    gemm_kernel<true><<<grid, NTHREADS, SM_TOTAL>>>(
        h1, adjc, W1, b1, ln2_w, ln2_b, nullptr, h2, N, n_tiles);
    // 3) out = gather(h2) @ W2 + b2 + x
    gemm_kernel<false><<<grid, NTHREADS, SM_TOTAL>>>(
        h2, adjc, W2, b2, nullptr, nullptr, x, out, N, n_tiles);
}